// round 2
// baseline (speedup 1.0000x reference)
#include <cuda_runtime.h>
#include <cuda_bf16.h>

#define BATCH 32768
#define HW 15
#define CELLS 225          // 15*15
#define PCODE 2380
#define SMROW 17           // 15 + 2 halo

__device__ __forceinline__ float lrelu16(float x) {
    return x >= 0.f ? x : x * 0.0625f;
}

__global__ void __launch_bounds__(256)
patnnue_kernel(const int* __restrict__ sparse,   // (B,12,15,15)
               const int* __restrict__ board,    // (B,2,15,15)
               const float* __restrict__ W_emb,  // (4762,8)
               const float* __restrict__ dw_w,   // (4,1,3,3)
               const float* __restrict__ dw_b,   // (4,)
               const float* __restrict__ pf_w,   // (1,4,1,1)
               const float* __restrict__ l1_w,   // (4,4)
               const float* __restrict__ l1_b,   // (4,)
               const float* __restrict__ l2_w,   // (4,4)
               const float* __restrict__ l2_b,   // (4,)
               const float* __restrict__ vf_w,   // (3,4)
               const float* __restrict__ vf_b,   // (3,)
               float* __restrict__ out_v,        // (B,3)
               float* __restrict__ out_p)        // (B,1,15,15)
{
    const int b = blockIdx.x;
    const int t = threadIdx.x;

    __shared__ float feat_s[4][SMROW][SMROW];   // policy channels, halo-padded
    __shared__ float vsum_s[4];

    // zero feature tile (halo must be 0 for SAME conv) and value accumulators
    float* fz = &feat_s[0][0][0];
    for (int i = t; i < 4 * SMROW * SMROW; i += blockDim.x) fz[i] = 0.f;
    if (t < 4) vsum_s[t] = 0.f;
    __syncthreads();

    float v4 = 0.f, v5 = 0.f, v6 = 0.f, v7 = 0.f;

    if (t < CELLS) {
        const int* sp = sparse + (long long)b * (12 * CELLS);
        const int* bd = board  + (long long)b * (2 * CELLS);

        int i0 = __ldg(sp + 10 * CELLS + t);
        int i1 = __ldg(sp + 11 * CELLS + t);
        int ne = (__ldg(bd + t) + __ldg(bd + CELLS + t)) > 0;
        if (ne) { i0 = PCODE; i1 = PCODE; }
        i1 += (PCODE + 1);

        // each embedding row = 8 floats = 32B, rows are 32B-aligned -> float4 x2
        float4 e0a = __ldg((const float4*)(W_emb + (size_t)i0 * 8));
        float4 e0b = __ldg((const float4*)(W_emb + (size_t)i0 * 8 + 4));
        float4 e1a = __ldg((const float4*)(W_emb + (size_t)i1 * 8));
        float4 e1b = __ldg((const float4*)(W_emb + (size_t)i1 * 8 + 4));

        const int y = t / HW, x = t % HW;
        feat_s[0][y + 1][x + 1] = e0a.x + e1a.x;
        feat_s[1][y + 1][x + 1] = e0a.y + e1a.y;
        feat_s[2][y + 1][x + 1] = e0a.z + e1a.z;
        feat_s[3][y + 1][x + 1] = e0a.w + e1a.w;
        v4 = e0b.x + e1b.x;
        v5 = e0b.y + e1b.y;
        v6 = e0b.z + e1b.z;
        v7 = e0b.w + e1b.w;
    }

    // warp-reduce value channels, then one smem atomic per warp per channel
    #pragma unroll
    for (int off = 16; off > 0; off >>= 1) {
        v4 += __shfl_down_sync(0xffffffffu, v4, off);
        v5 += __shfl_down_sync(0xffffffffu, v5, off);
        v6 += __shfl_down_sync(0xffffffffu, v6, off);
        v7 += __shfl_down_sync(0xffffffffu, v7, off);
    }
    if ((t & 31) == 0) {
        atomicAdd(&vsum_s[0], v4);
        atomicAdd(&vsum_s[1], v5);
        atomicAdd(&vsum_s[2], v6);
        atomicAdd(&vsum_s[3], v7);
    }
    __syncthreads();

    // depthwise 3x3 (SAME) + bias + relu, then pointwise 1x1 (4->1)
    if (t < CELLS) {
        const int y = t / HW, x = t % HW;
        float p = 0.f;
        #pragma unroll
        for (int c = 0; c < 4; c++) {
            float acc = __ldg(dw_b + c);
            #pragma unroll
            for (int ky = 0; ky < 3; ky++) {
                #pragma unroll
                for (int kx = 0; kx < 3; kx++) {
                    acc = fmaf(__ldg(dw_w + c * 9 + ky * 3 + kx),
                               feat_s[c][y + ky][x + kx], acc);
                }
            }
            p = fmaf(__ldg(pf_w + c), fmaxf(acc, 0.f), p);
        }
        out_p[(long long)b * CELLS + t] = p;
    }

    // value head MLP (thread 0)
    if (t == 0) {
        float v0 = vsum_s[0], v1 = vsum_s[1], v2 = vsum_s[2], v3 = vsum_s[3];
        float h[4], g[4];
        #pragma unroll
        for (int i = 0; i < 4; i++) {
            float a = __ldg(l1_b + i);
            a = fmaf(__ldg(l1_w + i * 4 + 0), v0, a);
            a = fmaf(__ldg(l1_w + i * 4 + 1), v1, a);
            a = fmaf(__ldg(l1_w + i * 4 + 2), v2, a);
            a = fmaf(__ldg(l1_w + i * 4 + 3), v3, a);
            h[i] = lrelu16(a);
        }
        #pragma unroll
        for (int i = 0; i < 4; i++) {
            float a = __ldg(l2_b + i);
            #pragma unroll
            for (int j = 0; j < 4; j++)
                a = fmaf(__ldg(l2_w + i * 4 + j), h[j], a);
            g[i] = lrelu16(a);
        }
        #pragma unroll
        for (int k = 0; k < 3; k++) {
            float a = __ldg(vf_b + k);
            #pragma unroll
            for (int j = 0; j < 4; j++)
                a = fmaf(__ldg(vf_w + k * 4 + j), g[j], a);
            out_v[(long long)b * 3 + k] = a;
        }
    }
}

extern "C" void kernel_launch(void* const* d_in, const int* in_sizes, int n_in,
                              void* d_out, int out_size) {
    const int*   sparse = (const int*)d_in[0];
    const int*   board  = (const int*)d_in[1];
    const float* W_emb  = (const float*)d_in[2];
    const float* dw_w   = (const float*)d_in[3];
    const float* dw_b   = (const float*)d_in[4];
    const float* pf_w   = (const float*)d_in[5];
    const float* l1_w   = (const float*)d_in[6];
    const float* l1_b   = (const float*)d_in[7];
    const float* l2_w   = (const float*)d_in[8];
    const float* l2_b   = (const float*)d_in[9];
    const float* vf_w   = (const float*)d_in[10];
    const float* vf_b   = (const float*)d_in[11];

    float* out   = (float*)d_out;
    float* out_v = out;                        // (B,3) first (tuple order)
    float* out_p = out + (size_t)BATCH * 3;    // (B,1,15,15) second

    patnnue_kernel<<<BATCH, 256>>>(sparse, board, W_emb, dw_w, dw_b, pf_w,
                                   l1_w, l1_b, l2_w, l2_b, vf_w, vf_b,
                                   out_v, out_p);
}

// round 3
// speedup vs baseline: 1.1743x; 1.1743x over previous
#include <cuda_runtime.h>
#include <cuda_bf16.h>

#define BATCH 32768
#define HW 15
#define CELLS 225          // 15*15
#define PCODE 2380
#define SMROW 17           // 15 + 2 halo

__device__ __forceinline__ float lrelu16(float x) {
    return x >= 0.f ? x : x * 0.0625f;
}

__device__ __forceinline__ float4 f4add(float4 a, float4 b) {
    return make_float4(a.x + b.x, a.y + b.y, a.z + b.z, a.w + b.w);
}

__global__ void __launch_bounds__(256)
patnnue_kernel(const int* __restrict__ sparse,   // (B,12,15,15)
               const int* __restrict__ board,    // (B,2,15,15)
               const float* __restrict__ W_emb,  // (4762,8)
               const float* __restrict__ dw_w,   // (4,1,3,3)
               const float* __restrict__ dw_b,   // (4,)
               const float* __restrict__ pf_w,   // (1,4,1,1)
               const float* __restrict__ l1_w,   // (4,4)
               const float* __restrict__ l1_b,   // (4,)
               const float* __restrict__ l2_w,   // (4,4)
               const float* __restrict__ l2_b,   // (4,)
               const float* __restrict__ vf_w,   // (3,4)
               const float* __restrict__ vf_b,   // (3,)
               float* __restrict__ out_v,        // (B,3)
               float* __restrict__ out_p)        // (B,1,15,15)
{
    const int b = blockIdx.x;
    const int t = threadIdx.x;

    __shared__ float4 feat4[SMROW][SMROW];   // policy channels packed, halo-padded
    __shared__ float4 wtap[9];               // dw weights, tap-major across channels
    __shared__ float4 wb4;                   // dw_b
    __shared__ float4 wpf4;                  // pf_w
    __shared__ float  vsum_s[4];

    // ---- stage weights (once per block, coalesced) ----
    if (t < 36) {
        float w = __ldg(dw_w + t);           // 36 contiguous floats -> 2 wavefronts
        int c = t / 9, tap = t % 9;
        ((float*)&wtap[tap])[c] = w;         // transpose to tap-major
    } else if (t == 36) {
        wb4  = __ldg((const float4*)dw_b);
    } else if (t == 37) {
        wpf4 = __ldg((const float4*)pf_w);
    }
    if (t < 4) vsum_s[t] = 0.f;

    // zero feature tile (halo must be 0 for SAME conv)
    float4* fz = &feat4[0][0];
    #pragma unroll
    for (int i = t; i < SMROW * SMROW; i += 256)
        fz[i] = make_float4(0.f, 0.f, 0.f, 0.f);
    __syncthreads();

    // constant row for non-empty cells: W_emb[PCODE] + W_emb[2*PCODE+1]
    // uniform addresses -> broadcast wavefronts, L1-resident
    float4 cpA = __ldg((const float4*)(W_emb + (size_t)PCODE * 8));
    float4 cvA = __ldg((const float4*)(W_emb + (size_t)PCODE * 8 + 4));
    float4 cpB = __ldg((const float4*)(W_emb + (size_t)(2 * PCODE + 1) * 8));
    float4 cvB = __ldg((const float4*)(W_emb + (size_t)(2 * PCODE + 1) * 8 + 4));
    const float4 cpol = f4add(cpA, cpB);
    const float4 cval = f4add(cvA, cvB);

    float v4 = 0.f, v5 = 0.f, v6 = 0.f, v7 = 0.f;

    if (t < CELLS) {
        const int* sp = sparse + (long long)b * (12 * CELLS);
        const int* bd = board  + (long long)b * (2 * CELLS);

        const int i0 = __ldg(sp + 10 * CELLS + t);
        const int i1 = __ldg(sp + 11 * CELLS + t);
        const bool ne = (__ldg(bd + t) + __ldg(bd + CELLS + t)) > 0;

        float4 fp, fv;
        if (ne) {           // ~75% of cells: no gather at all
            fp = cpol;
            fv = cval;
        } else {            // scattered gathers only for empty cells
            float4 a0 = __ldg((const float4*)(W_emb + (size_t)i0 * 8));
            float4 b0 = __ldg((const float4*)(W_emb + (size_t)i0 * 8 + 4));
            float4 a1 = __ldg((const float4*)(W_emb + (size_t)(i1 + PCODE + 1) * 8));
            float4 b1 = __ldg((const float4*)(W_emb + (size_t)(i1 + PCODE + 1) * 8 + 4));
            fp = f4add(a0, a1);
            fv = f4add(b0, b1);
        }

        const int y = t / HW, x = t % HW;
        feat4[y + 1][x + 1] = fp;            // one STS.128
        v4 = fv.x; v5 = fv.y; v6 = fv.z; v7 = fv.w;
    }

    // warp-reduce value channels, then one smem atomic per warp per channel
    #pragma unroll
    for (int off = 16; off > 0; off >>= 1) {
        v4 += __shfl_down_sync(0xffffffffu, v4, off);
        v5 += __shfl_down_sync(0xffffffffu, v5, off);
        v6 += __shfl_down_sync(0xffffffffu, v6, off);
        v7 += __shfl_down_sync(0xffffffffu, v7, off);
    }
    if ((t & 31) == 0) {
        atomicAdd(&vsum_s[0], v4);
        atomicAdd(&vsum_s[1], v5);
        atomicAdd(&vsum_s[2], v6);
        atomicAdd(&vsum_s[3], v7);
    }
    __syncthreads();

    // depthwise 3x3 (SAME) + bias + relu + pointwise 1x1, all 4 channels via float4
    if (t < CELLS) {
        const int y = t / HW, x = t % HW;
        float4 acc = wb4;
        #pragma unroll
        for (int ky = 0; ky < 3; ky++) {
            #pragma unroll
            for (int kx = 0; kx < 3; kx++) {
                const float4 w = wtap[ky * 3 + kx];   // broadcast LDS.128
                const float4 f = feat4[y + ky][x + kx];
                acc.x = fmaf(w.x, f.x, acc.x);
                acc.y = fmaf(w.y, f.y, acc.y);
                acc.z = fmaf(w.z, f.z, acc.z);
                acc.w = fmaf(w.w, f.w, acc.w);
            }
        }
        float p = wpf4.x * fmaxf(acc.x, 0.f)
                + wpf4.y * fmaxf(acc.y, 0.f)
                + wpf4.z * fmaxf(acc.z, 0.f)
                + wpf4.w * fmaxf(acc.w, 0.f);
        out_p[(long long)b * CELLS + t] = p;
    }

    // value head MLP (thread 0) — tiny, float4-vectorized weight loads
    if (t == 0) {
        const float v0 = vsum_s[0], v1 = vsum_s[1], v2 = vsum_s[2], v3 = vsum_s[3];
        const float4 l1b = __ldg((const float4*)l1_b);
        const float4 l2b = __ldg((const float4*)l2_b);
        float h[4], g[4];
        #pragma unroll
        for (int i = 0; i < 4; i++) {
            const float4 w = __ldg((const float4*)(l1_w + i * 4));
            float a = ((const float*)&l1b)[i];
            a = fmaf(w.x, v0, a); a = fmaf(w.y, v1, a);
            a = fmaf(w.z, v2, a); a = fmaf(w.w, v3, a);
            h[i] = lrelu16(a);
        }
        #pragma unroll
        for (int i = 0; i < 4; i++) {
            const float4 w = __ldg((const float4*)(l2_w + i * 4));
            float a = ((const float*)&l2b)[i];
            a = fmaf(w.x, h[0], a); a = fmaf(w.y, h[1], a);
            a = fmaf(w.z, h[2], a); a = fmaf(w.w, h[3], a);
            g[i] = lrelu16(a);
        }
        #pragma unroll
        for (int k = 0; k < 3; k++) {
            const float4 w = __ldg((const float4*)(vf_w + k * 4));
            float a = __ldg(vf_b + k);
            a = fmaf(w.x, g[0], a); a = fmaf(w.y, g[1], a);
            a = fmaf(w.z, g[2], a); a = fmaf(w.w, g[3], a);
            out_v[(long long)b * 3 + k] = a;
        }
    }
}

extern "C" void kernel_launch(void* const* d_in, const int* in_sizes, int n_in,
                              void* d_out, int out_size) {
    const int*   sparse = (const int*)d_in[0];
    const int*   board  = (const int*)d_in[1];
    const float* W_emb  = (const float*)d_in[2];
    const float* dw_w   = (const float*)d_in[3];
    const float* dw_b   = (const float*)d_in[4];
    const float* pf_w   = (const float*)d_in[5];
    const float* l1_w   = (const float*)d_in[6];
    const float* l1_b   = (const float*)d_in[7];
    const float* l2_w   = (const float*)d_in[8];
    const float* l2_b   = (const float*)d_in[9];
    const float* vf_w   = (const float*)d_in[10];
    const float* vf_b   = (const float*)d_in[11];

    float* out   = (float*)d_out;
    float* out_v = out;                        // (B,3) first (tuple order)
    float* out_p = out + (size_t)BATCH * 3;    // (B,1,15,15) second

    patnnue_kernel<<<BATCH, 256>>>(sparse, board, W_emb, dw_w, dw_b, pf_w,
                                   l1_w, l1_b, l2_w, l2_b, vf_w, vf_b,
                                   out_v, out_p);
}

// round 4
// speedup vs baseline: 1.4813x; 1.2615x over previous
#include <cuda_runtime.h>
#include <cuda_fp16.h>

#define BATCH 32768
#define HW 15
#define CELLS 225          // 15*15
#define PCODE 2380
#define NROWS (2 * (PCODE + 1))   // 4762 embedding rows
#define SMROW 17           // 15 + 2 halo

// fp16 embedding table: row = 8 halves = 16 bytes -> one LDG.128 per row
__device__ __align__(16) __half g_emb[NROWS * 8];

__global__ void __launch_bounds__(256)
emb_to_half_kernel(const float* __restrict__ W_emb) {
    int i = blockIdx.x * 256 + threadIdx.x;          // one half4 (4 floats) per thread
    if (i < NROWS * 2) {
        float4 f = __ldg((const float4*)(W_emb + (size_t)i * 4));
        __half2* dst = (__half2*)(g_emb + (size_t)i * 4);
        dst[0] = __floats2half2_rn(f.x, f.y);
        dst[1] = __floats2half2_rn(f.z, f.w);
    }
}

__device__ __forceinline__ float lrelu16(float x) {
    return x >= 0.f ? x : x * 0.0625f;
}

__global__ void __launch_bounds__(256)
patnnue_kernel(const int* __restrict__ sparse,   // (B,12,15,15)
               const int* __restrict__ board,    // (B,2,15,15)
               const float* __restrict__ dw_w,   // (4,1,3,3)
               const float* __restrict__ dw_b,   // (4,)
               const float* __restrict__ pf_w,   // (1,4,1,1)
               const float* __restrict__ l1_w,   // (4,4)
               const float* __restrict__ l1_b,   // (4,)
               const float* __restrict__ l2_w,   // (4,4)
               const float* __restrict__ l2_b,   // (4,)
               const float* __restrict__ vf_w,   // (3,4)
               const float* __restrict__ vf_b,   // (3,)
               float* __restrict__ out_v,        // (B,3)
               float* __restrict__ out_p)        // (B,1,15,15)
{
    const int b = blockIdx.x;
    const int t = threadIdx.x;

    __shared__ uint2  feat_s[SMROW][SMROW];  // 4 policy channels as half4 (8B)
    __shared__ float4 wtap[9];               // dw weights, tap-major across channels
    __shared__ float4 wb4;                   // dw_b
    __shared__ float4 wpf4;                  // pf_w
    __shared__ float  vsum_s[4];

    // ---- phase 0: halo zero + weight staging + vsum init ----
    if (t < 64) {                            // only the 64 halo slots need zeroing
        int hy, hx;
        if      (t < 17) { hy = 0;          hx = t;      }
        else if (t < 34) { hy = 16;         hx = t - 17; }
        else if (t < 49) { hy = t - 34 + 1; hx = 0;      }
        else             { hy = t - 49 + 1; hx = 16;     }
        feat_s[hy][hx] = make_uint2(0u, 0u);
    } else if (t < 100) {
        int i = t - 64;                      // 36 contiguous floats, coalesced
        float w = __ldg(dw_w + i);
        ((float*)&wtap[i % 9])[i / 9];       // (address only) — real store below
        ((float*)&wtap[i % 9])[i / 9] = w;   // transpose to tap-major
    } else if (t == 100) {
        wb4  = __ldg((const float4*)dw_b);
    } else if (t == 101) {
        wpf4 = __ldg((const float4*)pf_w);
    } else if (t >= 104 && t < 108) {
        vsum_s[t - 104] = 0.f;
    }
    __syncthreads();

    // ---- phase 1: branchless fp16 gather + feature build ----
    float v4 = 0.f, v5 = 0.f, v6 = 0.f, v7 = 0.f;

    if (t < CELLS) {
        const int* sp = sparse + (long long)b * (12 * CELLS);
        const int* bd = board  + (long long)b * (2 * CELLS);

        const int i0 = __ldg(sp + 10 * CELLS + t);
        const int i1 = __ldg(sp + 11 * CELLS + t);
        const bool ne = (__ldg(bd + t) + __ldg(bd + CELLS + t)) > 0;

        // non-empty lanes all point at the PCODE rows -> their lines merge to 1 wf
        const int r0 = ne ? PCODE : i0;
        const int r1 = (ne ? PCODE : i1) + (PCODE + 1);

        // one LDG.128 per row fetches all 8 channels
        uint4 e0 = __ldg((const uint4*)(g_emb + (size_t)r0 * 8));
        uint4 e1 = __ldg((const uint4*)(g_emb + (size_t)r1 * 8));

        float2 p01 = __half22float2(*(__half2*)&e0.x);
        float2 q01 = __half22float2(*(__half2*)&e1.x);
        float2 p23 = __half22float2(*(__half2*)&e0.y);
        float2 q23 = __half22float2(*(__half2*)&e1.y);
        float2 a45 = __half22float2(*(__half2*)&e0.z);
        float2 b45 = __half22float2(*(__half2*)&e1.z);
        float2 a67 = __half22float2(*(__half2*)&e0.w);
        float2 b67 = __half22float2(*(__half2*)&e1.w);

        // policy channels packed back to half4 for cheap smem (LDS.64 in conv)
        __half2 hp0 = __floats2half2_rn(p01.x + q01.x, p01.y + q01.y);
        __half2 hp1 = __floats2half2_rn(p23.x + q23.x, p23.y + q23.y);
        const int y = t / HW, x = t % HW;
        feat_s[y + 1][x + 1] = make_uint2(*(unsigned*)&hp0, *(unsigned*)&hp1);

        v4 = a45.x + b45.x;
        v5 = a45.y + b45.y;
        v6 = a67.x + b67.x;
        v7 = a67.y + b67.y;
    }

    // warp-reduce value channels, one smem atomic per warp per channel
    #pragma unroll
    for (int off = 16; off > 0; off >>= 1) {
        v4 += __shfl_down_sync(0xffffffffu, v4, off);
        v5 += __shfl_down_sync(0xffffffffu, v5, off);
        v6 += __shfl_down_sync(0xffffffffu, v6, off);
        v7 += __shfl_down_sync(0xffffffffu, v7, off);
    }
    if ((t & 31) == 0) {
        atomicAdd(&vsum_s[0], v4);
        atomicAdd(&vsum_s[1], v5);
        atomicAdd(&vsum_s[2], v6);
        atomicAdd(&vsum_s[3], v7);
    }
    __syncthreads();

    // ---- phase 2: depthwise 3x3 + relu + pointwise, fp32 math on half4 feats ----
    if (t < CELLS) {
        const int y = t / HW, x = t % HW;
        float4 acc = wb4;
        #pragma unroll
        for (int ky = 0; ky < 3; ky++) {
            #pragma unroll
            for (int kx = 0; kx < 3; kx++) {
                const float4 w = wtap[ky * 3 + kx];         // broadcast LDS.128
                const uint2  f = feat_s[y + ky][x + kx];    // LDS.64
                const float2 lo = __half22float2(*(__half2*)&f.x);
                const float2 hi = __half22float2(*(__half2*)&f.y);
                acc.x = fmaf(w.x, lo.x, acc.x);
                acc.y = fmaf(w.y, lo.y, acc.y);
                acc.z = fmaf(w.z, hi.x, acc.z);
                acc.w = fmaf(w.w, hi.y, acc.w);
            }
        }
        float p = wpf4.x * fmaxf(acc.x, 0.f)
                + wpf4.y * fmaxf(acc.y, 0.f)
                + wpf4.z * fmaxf(acc.z, 0.f)
                + wpf4.w * fmaxf(acc.w, 0.f);
        out_p[(long long)b * CELLS + t] = p;
    }

    // ---- value head MLP (thread 0) ----
    if (t == 0) {
        const float v0 = vsum_s[0], v1 = vsum_s[1], v2 = vsum_s[2], v3 = vsum_s[3];
        const float4 l1b = __ldg((const float4*)l1_b);
        const float4 l2b = __ldg((const float4*)l2_b);
        float h[4], g[4];
        #pragma unroll
        for (int i = 0; i < 4; i++) {
            const float4 w = __ldg((const float4*)(l1_w + i * 4));
            float a = ((const float*)&l1b)[i];
            a = fmaf(w.x, v0, a); a = fmaf(w.y, v1, a);
            a = fmaf(w.z, v2, a); a = fmaf(w.w, v3, a);
            h[i] = lrelu16(a);
        }
        #pragma unroll
        for (int i = 0; i < 4; i++) {
            const float4 w = __ldg((const float4*)(l2_w + i * 4));
            float a = ((const float*)&l2b)[i];
            a = fmaf(w.x, h[0], a); a = fmaf(w.y, h[1], a);
            a = fmaf(w.z, h[2], a); a = fmaf(w.w, h[3], a);
            g[i] = lrelu16(a);
        }
        #pragma unroll
        for (int k = 0; k < 3; k++) {
            const float4 w = __ldg((const float4*)(vf_w + k * 4));
            float a = __ldg(vf_b + k);
            a = fmaf(w.x, g[0], a); a = fmaf(w.y, g[1], a);
            a = fmaf(w.z, g[2], a); a = fmaf(w.w, g[3], a);
            out_v[(long long)b * 3 + k] = a;
        }
    }
}

extern "C" void kernel_launch(void* const* d_in, const int* in_sizes, int n_in,
                              void* d_out, int out_size) {
    const int*   sparse = (const int*)d_in[0];
    const int*   board  = (const int*)d_in[1];
    const float* W_emb  = (const float*)d_in[2];
    const float* dw_w   = (const float*)d_in[3];
    const float* dw_b   = (const float*)d_in[4];
    const float* pf_w   = (const float*)d_in[5];
    const float* l1_w   = (const float*)d_in[6];
    const float* l1_b   = (const float*)d_in[7];
    const float* l2_w   = (const float*)d_in[8];
    const float* l2_b   = (const float*)d_in[9];
    const float* vf_w   = (const float*)d_in[10];
    const float* vf_b   = (const float*)d_in[11];

    float* out   = (float*)d_out;
    float* out_v = out;                        // (B,3) first (tuple order)
    float* out_p = out + (size_t)BATCH * 3;    // (B,1,15,15) second

    // build fp16 embedding table (graph-capturable: plain kernel launch)
    emb_to_half_kernel<<<(NROWS * 2 + 255) / 256, 256>>>(W_emb);

    patnnue_kernel<<<BATCH, 256>>>(sparse, board, dw_w, dw_b, pf_w,
                                   l1_w, l1_b, l2_w, l2_b, vf_w, vf_b,
                                   out_v, out_p);
}

// round 5
// speedup vs baseline: 1.6897x; 1.1406x over previous
#include <cuda_runtime.h>
#include <cuda_fp16.h>

#define BATCH 32768
#define HW 15
#define CELLS 225          // 15*15
#define PCODE 2380
#define NROWS (2 * (PCODE + 1))   // 4762 embedding rows
#define SMROW 17           // 15 + 2 halo
#define SMCOL 18           // padded to even (16B-aligned uint4 pairs)

// fp16 embedding table: row = 8 halves = 16 bytes -> one LDG.128 per row
__device__ __align__(16) __half g_emb[NROWS * 8];

__global__ void __launch_bounds__(256)
emb_to_half_kernel(const float* __restrict__ W_emb) {
    int i = blockIdx.x * 256 + threadIdx.x;          // one half4 (4 floats) per thread
    if (i < NROWS * 2) {
        float4 f = __ldg((const float4*)(W_emb + (size_t)i * 4));
        __half2* dst = (__half2*)(g_emb + (size_t)i * 4);
        dst[0] = __floats2half2_rn(f.x, f.y);
        dst[1] = __floats2half2_rn(f.z, f.w);
    }
}

__device__ __forceinline__ float lrelu16(float x) {
    return x >= 0.f ? x : x * 0.0625f;
}

__device__ __forceinline__ void unpack_cell(unsigned lo, unsigned hi, float* out) {
    float2 a = __half22float2(*(__half2*)&lo);
    float2 b = __half22float2(*(__half2*)&hi);
    out[0] = a.x; out[1] = a.y; out[2] = b.x; out[3] = b.y;
}

__global__ void __launch_bounds__(256)
patnnue_kernel(const int* __restrict__ sparse,   // (B,12,15,15)
               const int* __restrict__ board,    // (B,2,15,15)
               const float* __restrict__ dw_w,   // (4,1,3,3)
               const float* __restrict__ dw_b,   // (4,)
               const float* __restrict__ pf_w,   // (1,4,1,1)
               const float* __restrict__ l1_w,   // (4,4)
               const float* __restrict__ l1_b,   // (4,)
               const float* __restrict__ l2_w,   // (4,4)
               const float* __restrict__ l2_b,   // (4,)
               const float* __restrict__ vf_w,   // (3,4)
               const float* __restrict__ vf_b,   // (3,)
               float* __restrict__ out_v,        // (B,3)
               float* __restrict__ out_p)        // (B,1,15,15)
{
    const int b = blockIdx.x;
    const int t = threadIdx.x;

    __shared__ __align__(16) uint2 feat_s[SMROW][SMCOL]; // 4 ch as half4 (8B)
    __shared__ float4 wtap[9];               // dw weights, tap-major across channels
    __shared__ float4 wb4;                   // dw_b
    __shared__ float4 wpf4;                  // pf_w
    __shared__ float  vsum_s[4];

    // ---- phase 0: halo/pad zero + weight staging + vsum init ----
    // halo slots: row0 (18) + row16 (18) + col0 rows1..15 (15) + cols16,17 rows1..15 (30) = 81
    if (t < 81) {
        int hy, hx;
        if      (t < 18) { hy = 0;  hx = t; }
        else if (t < 36) { hy = 16; hx = t - 18; }
        else if (t < 51) { hy = t - 36 + 1; hx = 0; }
        else             { int u = t - 51; hy = (u >> 1) + 1; hx = 16 + (u & 1); }
        feat_s[hy][hx] = make_uint2(0u, 0u);
    } else if (t < 128) {
        int i = t - 92;                      // threads 92..127 -> 36 dw weights
        if (i >= 0) {
            float w = __ldg(dw_w + i);
            ((float*)&wtap[i % 9])[i / 9] = w;   // transpose to tap-major
        }
    } else if (t == 128) {
        wb4  = __ldg((const float4*)dw_b);
    } else if (t == 129) {
        wpf4 = __ldg((const float4*)pf_w);
    } else if (t >= 132 && t < 136) {
        vsum_s[t - 132] = 0.f;
    }
    __syncthreads();

    // ---- phase 1: branchless fp16 gather + feature build (thread = cell) ----
    float v4 = 0.f, v5 = 0.f, v6 = 0.f, v7 = 0.f;

    if (t < CELLS) {
        const int* sp = sparse + (long long)b * (12 * CELLS);
        const int* bd = board  + (long long)b * (2 * CELLS);

        const int i0 = __ldg(sp + 10 * CELLS + t);
        const int i1 = __ldg(sp + 11 * CELLS + t);
        const bool ne = (__ldg(bd + t) + __ldg(bd + CELLS + t)) > 0;

        // non-empty lanes all point at the PCODE rows -> their lines merge to 1 wf
        const int r0 = ne ? PCODE : i0;
        const int r1 = (ne ? PCODE : i1) + (PCODE + 1);

        uint4 e0 = __ldg((const uint4*)(g_emb + (size_t)r0 * 8));
        uint4 e1 = __ldg((const uint4*)(g_emb + (size_t)r1 * 8));

        float2 p01 = __half22float2(*(__half2*)&e0.x);
        float2 q01 = __half22float2(*(__half2*)&e1.x);
        float2 p23 = __half22float2(*(__half2*)&e0.y);
        float2 q23 = __half22float2(*(__half2*)&e1.y);
        float2 a45 = __half22float2(*(__half2*)&e0.z);
        float2 b45 = __half22float2(*(__half2*)&e1.z);
        float2 a67 = __half22float2(*(__half2*)&e0.w);
        float2 b67 = __half22float2(*(__half2*)&e1.w);

        __half2 hp0 = __floats2half2_rn(p01.x + q01.x, p01.y + q01.y);
        __half2 hp1 = __floats2half2_rn(p23.x + q23.x, p23.y + q23.y);
        const int y = t / HW, x = t % HW;
        feat_s[y + 1][x + 1] = make_uint2(*(unsigned*)&hp0, *(unsigned*)&hp1);

        v4 = a45.x + b45.x;
        v5 = a45.y + b45.y;
        v6 = a67.x + b67.x;
        v7 = a67.y + b67.y;
    }

    // warp-reduce value channels, one smem atomic per warp per channel
    #pragma unroll
    for (int off = 16; off > 0; off >>= 1) {
        v4 += __shfl_down_sync(0xffffffffu, v4, off);
        v5 += __shfl_down_sync(0xffffffffu, v5, off);
        v6 += __shfl_down_sync(0xffffffffu, v6, off);
        v7 += __shfl_down_sync(0xffffffffu, v7, off);
    }
    if ((t & 31) == 0) {
        atomicAdd(&vsum_s[0], v4);
        atomicAdd(&vsum_s[1], v5);
        atomicAdd(&vsum_s[2], v6);
        atomicAdd(&vsum_s[3], v7);
    }
    __syncthreads();

    // ---- phase 2: conv, 2 output cells per thread, paired LDS.128 reads ----
    // t < 120: y = t/8 (0..14), j = t%8, x0 = 2j. Lanes 0..7 of each warp share a
    // row -> every LDS.128 phase is a contiguous conflict-free 128B.
    if (t < 120) {
        const int y  = t >> 3;
        const int j  = t & 7;
        const int x0 = j << 1;

        float4 acc0 = wb4, acc1 = wb4;
        #pragma unroll
        for (int r = 0; r < 3; r++) {
            const uint4* rowp = (const uint4*)&feat_s[y + r][x0];
            uint4 A = rowp[0];                   // cells x0, x0+1
            uint4 B = rowp[1];                   // cells x0+2, x0+3
            float c[4][4];
            unpack_cell(A.x, A.y, c[0]);
            unpack_cell(A.z, A.w, c[1]);
            unpack_cell(B.x, B.y, c[2]);
            unpack_cell(B.z, B.w, c[3]);
            #pragma unroll
            for (int kx = 0; kx < 3; kx++) {
                const float4 w = wtap[r * 3 + kx];   // broadcast LDS.128
                acc0.x = fmaf(w.x, c[kx][0],     acc0.x);
                acc0.y = fmaf(w.y, c[kx][1],     acc0.y);
                acc0.z = fmaf(w.z, c[kx][2],     acc0.z);
                acc0.w = fmaf(w.w, c[kx][3],     acc0.w);
                acc1.x = fmaf(w.x, c[kx + 1][0], acc1.x);
                acc1.y = fmaf(w.y, c[kx + 1][1], acc1.y);
                acc1.z = fmaf(w.z, c[kx + 1][2], acc1.z);
                acc1.w = fmaf(w.w, c[kx + 1][3], acc1.w);
            }
        }
        float p0 = wpf4.x * fmaxf(acc0.x, 0.f)
                 + wpf4.y * fmaxf(acc0.y, 0.f)
                 + wpf4.z * fmaxf(acc0.z, 0.f)
                 + wpf4.w * fmaxf(acc0.w, 0.f);
        const long long base = (long long)b * CELLS + y * HW + x0;
        out_p[base] = p0;
        if (j < 7) {                              // x0+1 valid only for j<7
            float p1 = wpf4.x * fmaxf(acc1.x, 0.f)
                     + wpf4.y * fmaxf(acc1.y, 0.f)
                     + wpf4.z * fmaxf(acc1.z, 0.f)
                     + wpf4.w * fmaxf(acc1.w, 0.f);
            out_p[base + 1] = p1;
        }
    }

    // ---- value head MLP on t=255 (warp 7 idle during conv) ----
    if (t == 255) {
        const float v0 = vsum_s[0], v1 = vsum_s[1], v2 = vsum_s[2], v3 = vsum_s[3];
        const float4 l1b = __ldg((const float4*)l1_b);
        const float4 l2b = __ldg((const float4*)l2_b);
        float h[4], g[4];
        #pragma unroll
        for (int i = 0; i < 4; i++) {
            const float4 w = __ldg((const float4*)(l1_w + i * 4));
            float a = ((const float*)&l1b)[i];
            a = fmaf(w.x, v0, a); a = fmaf(w.y, v1, a);
            a = fmaf(w.z, v2, a); a = fmaf(w.w, v3, a);
            h[i] = lrelu16(a);
        }
        #pragma unroll
        for (int i = 0; i < 4; i++) {
            const float4 w = __ldg((const float4*)(l2_w + i * 4));
            float a = ((const float*)&l2b)[i];
            a = fmaf(w.x, h[0], a); a = fmaf(w.y, h[1], a);
            a = fmaf(w.z, h[2], a); a = fmaf(w.w, h[3], a);
            g[i] = lrelu16(a);
        }
        #pragma unroll
        for (int k = 0; k < 3; k++) {
            const float4 w = __ldg((const float4*)(vf_w + k * 4));
            float a = __ldg(vf_b + k);
            a = fmaf(w.x, g[0], a); a = fmaf(w.y, g[1], a);
            a = fmaf(w.z, g[2], a); a = fmaf(w.w, g[3], a);
            out_v[(long long)b * 3 + k] = a;
        }
    }
}

extern "C" void kernel_launch(void* const* d_in, const int* in_sizes, int n_in,
                              void* d_out, int out_size) {
    const int*   sparse = (const int*)d_in[0];
    const int*   board  = (const int*)d_in[1];
    const float* W_emb  = (const float*)d_in[2];
    const float* dw_w   = (const float*)d_in[3];
    const float* dw_b   = (const float*)d_in[4];
    const float* pf_w   = (const float*)d_in[5];
    const float* l1_w   = (const float*)d_in[6];
    const float* l1_b   = (const float*)d_in[7];
    const float* l2_w   = (const float*)d_in[8];
    const float* l2_b   = (const float*)d_in[9];
    const float* vf_w   = (const float*)d_in[10];
    const float* vf_b   = (const float*)d_in[11];

    float* out   = (float*)d_out;
    float* out_v = out;                        // (B,3) first (tuple order)
    float* out_p = out + (size_t)BATCH * 3;    // (B,1,15,15) second

    emb_to_half_kernel<<<(NROWS * 2 + 255) / 256, 256>>>(W_emb);

    patnnue_kernel<<<BATCH, 256>>>(sparse, board, dw_w, dw_b, pf_w,
                                   l1_w, l1_b, l2_w, l2_b, vf_w, vf_b,
                                   out_v, out_p);
}

// round 6
// speedup vs baseline: 2.2273x; 1.3182x over previous
#include <cuda_runtime.h>
#include <cuda_fp16.h>

#define BATCH 32768
#define HW 15
#define CELLS 225          // 15*15
#define PCODE 2380
#define NROWS (2 * (PCODE + 1))   // 4762 embedding rows
#define SMROW 17           // 15 + 2 halo
#define SMCOL 18           // padded to even (16B-aligned uint4 pairs)

// fp16 embedding table: row = 8 halves = 16 bytes -> one LDG.128 per row
__device__ __align__(16) __half g_emb[NROWS * 8];

__global__ void __launch_bounds__(256)
emb_to_half_kernel(const float* __restrict__ W_emb) {
    int i = blockIdx.x * 256 + threadIdx.x;          // one half4 (4 floats) per thread
    if (i < NROWS * 2) {
        float4 f = __ldg((const float4*)(W_emb + (size_t)i * 4));
        __half2* dst = (__half2*)(g_emb + (size_t)i * 4);
        dst[0] = __floats2half2_rn(f.x, f.y);
        dst[1] = __floats2half2_rn(f.z, f.w);
    }
}

__device__ __forceinline__ float lrelu16(float x) {
    return x >= 0.f ? x : x * 0.0625f;
}

__device__ __forceinline__ void unpack_cell(unsigned lo, unsigned hi, float* out) {
    float2 a = __half22float2(*(__half2*)&lo);
    float2 b = __half22float2(*(__half2*)&hi);
    out[0] = a.x; out[1] = a.y; out[2] = b.x; out[3] = b.y;
}

// gather one cell's two fp16 embedding rows, emit packed policy half4 + value f32x4
__device__ __forceinline__ void gather_cell(int r0, int r1, uint2* pol,
                                            float& v4, float& v5, float& v6, float& v7) {
    uint4 e0 = __ldg((const uint4*)(g_emb + (size_t)r0 * 8));
    uint4 e1 = __ldg((const uint4*)(g_emb + (size_t)r1 * 8));
    float2 p01 = __half22float2(*(__half2*)&e0.x);
    float2 q01 = __half22float2(*(__half2*)&e1.x);
    float2 p23 = __half22float2(*(__half2*)&e0.y);
    float2 q23 = __half22float2(*(__half2*)&e1.y);
    float2 a45 = __half22float2(*(__half2*)&e0.z);
    float2 b45 = __half22float2(*(__half2*)&e1.z);
    float2 a67 = __half22float2(*(__half2*)&e0.w);
    float2 b67 = __half22float2(*(__half2*)&e1.w);
    __half2 hp0 = __floats2half2_rn(p01.x + q01.x, p01.y + q01.y);
    __half2 hp1 = __floats2half2_rn(p23.x + q23.x, p23.y + q23.y);
    *pol = make_uint2(*(unsigned*)&hp0, *(unsigned*)&hp1);
    v4 += a45.x + b45.x;
    v5 += a45.y + b45.y;
    v6 += a67.x + b67.x;
    v7 += a67.y + b67.y;
}

__global__ void __launch_bounds__(128, 8)
patnnue_kernel(const int* __restrict__ sparse,   // (B,12,15,15)
               const int* __restrict__ board,    // (B,2,15,15)
               const float* __restrict__ dw_w,   // (4,1,3,3)
               const float* __restrict__ dw_b,   // (4,)
               const float* __restrict__ pf_w,   // (1,4,1,1)
               const float* __restrict__ l1_w,   // (4,4)
               const float* __restrict__ l1_b,   // (4,)
               const float* __restrict__ l2_w,   // (4,4)
               const float* __restrict__ l2_b,   // (4,)
               const float* __restrict__ vf_w,   // (3,4)
               const float* __restrict__ vf_b,   // (3,)
               float* __restrict__ out_v,        // (B,3)
               float* __restrict__ out_p)        // (B,1,15,15)
{
    const int b = blockIdx.x;
    const int t = threadIdx.x;

    __shared__ __align__(16) uint2 feat_s[SMROW][SMCOL]; // 4 ch as half4 (8B)
    __shared__ float4 wtap[9];               // dw weights, tap-major across channels
    __shared__ float4 wb4;                   // dw_b
    __shared__ float4 wpf4;                  // pf_w
    __shared__ float4 vsum_w[4];             // per-warp value partials

    // ---- phase 0: halo/pad zero + weight staging ----
    // halo slots: row0(18) + row16(18) + col0 rows1..15 (15) + cols16,17 rows1..15 (30) = 81
    if (t < 81) {
        int hy, hx;
        if      (t < 18) { hy = 0;  hx = t; }
        else if (t < 36) { hy = 16; hx = t - 18; }
        else if (t < 51) { hy = t - 36 + 1; hx = 0; }
        else             { int u = t - 51; hy = (u >> 1) + 1; hx = 16 + (u & 1); }
        feat_s[hy][hx] = make_uint2(0u, 0u);
    } else if (t < 117) {
        int i = t - 81;                      // 36 contiguous dw weights, coalesced
        float w = __ldg(dw_w + i);
        ((float*)&wtap[i % 9])[i / 9] = w;   // transpose to tap-major
    } else if (t == 117) {
        wb4  = __ldg((const float4*)dw_b);
    } else if (t == 118) {
        wpf4 = __ldg((const float4*)pf_w);
    }
    __syncthreads();

    // ---- phase 1: 2 adjacent cells per thread, branchless fp16 gathers ----
    float v4 = 0.f, v5 = 0.f, v6 = 0.f, v7 = 0.f;

    if (t < 113) {                            // cells 2t, 2t+1 (cell 225 doesn't exist)
        const int* sp = sparse + (long long)b * (12 * CELLS);
        const int* bd = board  + (long long)b * (2 * CELLS);
        const int c0 = 2 * t;
        const bool has1 = (t < 112);          // c1 = c0+1 valid

        // aligned int2 loads for even-offset channels (ch10 @2250, board ch0 @0)
        int2 i0p = __ldg((const int2*)(sp + 10 * CELLS) + t);
        int2 b0p = __ldg((const int2*)bd + t);
        // odd-offset channels: scalar (still coalesced)
        int i1a = __ldg(sp + 11 * CELLS + c0);
        int b1a = __ldg(bd + CELLS + c0);
        int i1b = 0, b1b = 0;
        if (has1) {
            i1b = __ldg(sp + 11 * CELLS + c0 + 1);
            b1b = __ldg(bd + CELLS + c0 + 1);
        }

        const bool ne0 = (b0p.x + b1a) > 0;
        const int r0a = ne0 ? PCODE : i0p.x;
        const int r0b = (ne0 ? PCODE : i1a) + (PCODE + 1);

        uint2 pol0;
        gather_cell(r0a, r0b, &pol0, v4, v5, v6, v7);
        {
            const int y = c0 / HW, x = c0 % HW;
            feat_s[y + 1][x + 1] = pol0;
        }

        if (has1) {
            const bool ne1 = (b0p.y + b1b) > 0;
            const int r1a = ne1 ? PCODE : i0p.y;
            const int r1b = (ne1 ? PCODE : i1b) + (PCODE + 1);
            uint2 pol1;
            gather_cell(r1a, r1b, &pol1, v4, v5, v6, v7);
            const int c1 = c0 + 1;
            const int y = c1 / HW, x = c1 % HW;
            feat_s[y + 1][x + 1] = pol1;
        }
    }

    // warp-reduce value channels; lane 0 of each warp stores a float4 partial
    #pragma unroll
    for (int off = 16; off > 0; off >>= 1) {
        v4 += __shfl_down_sync(0xffffffffu, v4, off);
        v5 += __shfl_down_sync(0xffffffffu, v5, off);
        v6 += __shfl_down_sync(0xffffffffu, v6, off);
        v7 += __shfl_down_sync(0xffffffffu, v7, off);
    }
    if ((t & 31) == 0)
        vsum_w[t >> 5] = make_float4(v4, v5, v6, v7);
    __syncthreads();

    // ---- phase 2: conv, 2 output cells per thread, paired LDS.128 reads ----
    if (t < 120) {
        const int y  = t >> 3;
        const int j  = t & 7;
        const int x0 = j << 1;

        float4 acc0 = wb4, acc1 = wb4;
        #pragma unroll
        for (int r = 0; r < 3; r++) {
            const uint4* rowp = (const uint4*)&feat_s[y + r][x0];
            uint4 A = rowp[0];                   // cells x0, x0+1
            uint4 B = rowp[1];                   // cells x0+2, x0+3
            float c[4][4];
            unpack_cell(A.x, A.y, c[0]);
            unpack_cell(A.z, A.w, c[1]);
            unpack_cell(B.x, B.y, c[2]);
            unpack_cell(B.z, B.w, c[3]);
            #pragma unroll
            for (int kx = 0; kx < 3; kx++) {
                const float4 w = wtap[r * 3 + kx];   // broadcast LDS.128
                acc0.x = fmaf(w.x, c[kx][0],     acc0.x);
                acc0.y = fmaf(w.y, c[kx][1],     acc0.y);
                acc0.z = fmaf(w.z, c[kx][2],     acc0.z);
                acc0.w = fmaf(w.w, c[kx][3],     acc0.w);
                acc1.x = fmaf(w.x, c[kx + 1][0], acc1.x);
                acc1.y = fmaf(w.y, c[kx + 1][1], acc1.y);
                acc1.z = fmaf(w.z, c[kx + 1][2], acc1.z);
                acc1.w = fmaf(w.w, c[kx + 1][3], acc1.w);
            }
        }
        float p0 = wpf4.x * fmaxf(acc0.x, 0.f)
                 + wpf4.y * fmaxf(acc0.y, 0.f)
                 + wpf4.z * fmaxf(acc0.z, 0.f)
                 + wpf4.w * fmaxf(acc0.w, 0.f);
        const long long base = (long long)b * CELLS + y * HW + x0;
        out_p[base] = p0;
        if (j < 7) {
            float p1 = wpf4.x * fmaxf(acc1.x, 0.f)
                     + wpf4.y * fmaxf(acc1.y, 0.f)
                     + wpf4.z * fmaxf(acc1.z, 0.f)
                     + wpf4.w * fmaxf(acc1.w, 0.f);
            out_p[base + 1] = p1;
        }
    } else if (t == 120) {
        // ---- value head MLP (thread idle in conv) ----
        float4 s0 = vsum_w[0], s1 = vsum_w[1], s2 = vsum_w[2], s3 = vsum_w[3];
        const float v0 = s0.x + s1.x + s2.x + s3.x;
        const float v1 = s0.y + s1.y + s2.y + s3.y;
        const float v2 = s0.z + s1.z + s2.z + s3.z;
        const float v3 = s0.w + s1.w + s2.w + s3.w;
        const float4 l1b = __ldg((const float4*)l1_b);
        const float4 l2b = __ldg((const float4*)l2_b);
        float h[4], g[4];
        #pragma unroll
        for (int i = 0; i < 4; i++) {
            const float4 w = __ldg((const float4*)(l1_w + i * 4));
            float a = ((const float*)&l1b)[i];
            a = fmaf(w.x, v0, a); a = fmaf(w.y, v1, a);
            a = fmaf(w.z, v2, a); a = fmaf(w.w, v3, a);
            h[i] = lrelu16(a);
        }
        #pragma unroll
        for (int i = 0; i < 4; i++) {
            const float4 w = __ldg((const float4*)(l2_w + i * 4));
            float a = ((const float*)&l2b)[i];
            a = fmaf(w.x, h[0], a); a = fmaf(w.y, h[1], a);
            a = fmaf(w.z, h[2], a); a = fmaf(w.w, h[3], a);
            g[i] = lrelu16(a);
        }
        #pragma unroll
        for (int k = 0; k < 3; k++) {
            const float4 w = __ldg((const float4*)(vf_w + k * 4));
            float a = __ldg(vf_b + k);
            a = fmaf(w.x, g[0], a); a = fmaf(w.y, g[1], a);
            a = fmaf(w.z, g[2], a); a = fmaf(w.w, g[3], a);
            out_v[(long long)b * 3 + k] = a;
        }
    }
}

extern "C" void kernel_launch(void* const* d_in, const int* in_sizes, int n_in,
                              void* d_out, int out_size) {
    const int*   sparse = (const int*)d_in[0];
    const int*   board  = (const int*)d_in[1];
    const float* W_emb  = (const float*)d_in[2];
    const float* dw_w   = (const float*)d_in[3];
    const float* dw_b   = (const float*)d_in[4];
    const float* pf_w   = (const float*)d_in[5];
    const float* l1_w   = (const float*)d_in[6];
    const float* l1_b   = (const float*)d_in[7];
    const float* l2_w   = (const float*)d_in[8];
    const float* l2_b   = (const float*)d_in[9];
    const float* vf_w   = (const float*)d_in[10];
    const float* vf_b   = (const float*)d_in[11];

    float* out   = (float*)d_out;
    float* out_v = out;                        // (B,3) first (tuple order)
    float* out_p = out + (size_t)BATCH * 3;    // (B,1,15,15) second

    emb_to_half_kernel<<<(NROWS * 2 + 255) / 256, 256>>>(W_emb);

    patnnue_kernel<<<BATCH, 128>>>(sparse, board, dw_w, dw_b, pf_w,
                                   l1_w, l1_b, l2_w, l2_b, vf_w, vf_b,
                                   out_v, out_p);
}

// round 7
// speedup vs baseline: 2.5301x; 1.1359x over previous
#include <cuda_runtime.h>
#include <cuda_fp16.h>

#define BATCH 32768
#define HW 15
#define CELLS 225          // 15*15
#define PCODE 2380
#define NROWS (2 * (PCODE + 1))   // 4762 embedding rows
#define SMROW 17           // 15 + 2 halo
#define SMCOL 18           // padded to even (16B-aligned uint4 pairs)
#define GRID_P 1184        // 148 SMs * 8 resident blocks

// fp16 embedding table: row = 8 halves = 16 bytes -> one LDG.128 per row
__device__ __align__(16) __half g_emb[NROWS * 8];

__global__ void __launch_bounds__(256)
emb_to_half_kernel(const float* __restrict__ W_emb) {
    int i = blockIdx.x * 256 + threadIdx.x;          // one half4 (4 floats) per thread
    if (i < NROWS * 2) {
        float4 f = __ldg((const float4*)(W_emb + (size_t)i * 4));
        __half2* dst = (__half2*)(g_emb + (size_t)i * 4);
        dst[0] = __floats2half2_rn(f.x, f.y);
        dst[1] = __floats2half2_rn(f.z, f.w);
    }
}

__device__ __forceinline__ float lrelu16(float x) {
    return x >= 0.f ? x : x * 0.0625f;
}

__device__ __forceinline__ void unpack_cell(unsigned lo, unsigned hi, float* out) {
    float2 a = __half22float2(*(__half2*)&lo);
    float2 b = __half22float2(*(__half2*)&hi);
    out[0] = a.x; out[1] = a.y; out[2] = b.x; out[3] = b.y;
}

// gather one cell's two fp16 embedding rows, emit packed policy half4 + value f32x4
__device__ __forceinline__ void gather_cell(int r0, int r1, uint2* pol,
                                            float& v4, float& v5, float& v6, float& v7) {
    uint4 e0 = __ldg((const uint4*)(g_emb + (size_t)r0 * 8));
    uint4 e1 = __ldg((const uint4*)(g_emb + (size_t)r1 * 8));
    float2 p01 = __half22float2(*(__half2*)&e0.x);
    float2 q01 = __half22float2(*(__half2*)&e1.x);
    float2 p23 = __half22float2(*(__half2*)&e0.y);
    float2 q23 = __half22float2(*(__half2*)&e1.y);
    float2 a45 = __half22float2(*(__half2*)&e0.z);
    float2 b45 = __half22float2(*(__half2*)&e1.z);
    float2 a67 = __half22float2(*(__half2*)&e0.w);
    float2 b67 = __half22float2(*(__half2*)&e1.w);
    __half2 hp0 = __floats2half2_rn(p01.x + q01.x, p01.y + q01.y);
    __half2 hp1 = __floats2half2_rn(p23.x + q23.x, p23.y + q23.y);
    *pol = make_uint2(*(unsigned*)&hp0, *(unsigned*)&hp1);
    v4 += a45.x + b45.x;
    v5 += a45.y + b45.y;
    v6 += a67.x + b67.x;
    v7 += a67.y + b67.y;
}

__global__ void __launch_bounds__(128, 8)
patnnue_kernel(const int* __restrict__ sparse,   // (B,12,15,15)
               const int* __restrict__ board,    // (B,2,15,15)
               const float* __restrict__ dw_w,   // (4,1,3,3)
               const float* __restrict__ dw_b,   // (4,)
               const float* __restrict__ pf_w,   // (1,4,1,1)
               const float* __restrict__ l1_w,   // (4,4)
               const float* __restrict__ l1_b,   // (4,)
               const float* __restrict__ l2_w,   // (4,4)
               const float* __restrict__ l2_b,   // (4,)
               const float* __restrict__ vf_w,   // (3,4)
               const float* __restrict__ vf_b,   // (3,)
               float* __restrict__ out_v,        // (B,3)
               float* __restrict__ out_p)        // (B,1,15,15)
{
    const int t = threadIdx.x;

    __shared__ __align__(16) uint2 feat_s[2][SMROW][SMCOL]; // double-buffered tile
    __shared__ float4 wtap[9];               // dw weights, tap-major across channels
    __shared__ float4 wb4;                   // dw_b
    __shared__ float4 wpf4;                  // pf_w
    __shared__ float4 vsum_w[2][4];          // per-warp value partials, double-buffered

    // ---- one-time init: halo zero (both buffers) + weight staging ----
    if (t < 81) {
        int hy, hx;
        if      (t < 18) { hy = 0;  hx = t; }
        else if (t < 36) { hy = 16; hx = t - 18; }
        else if (t < 51) { hy = t - 36 + 1; hx = 0; }
        else             { int u = t - 51; hy = (u >> 1) + 1; hx = 16 + (u & 1); }
        feat_s[0][hy][hx] = make_uint2(0u, 0u);
        feat_s[1][hy][hx] = make_uint2(0u, 0u);
    } else if (t < 117) {
        int i = t - 81;                      // 36 contiguous dw weights, coalesced
        float w = __ldg(dw_w + i);
        ((float*)&wtap[i % 9])[i / 9] = w;   // transpose to tap-major
    } else if (t == 117) {
        wb4  = __ldg((const float4*)dw_b);
    } else if (t == 118) {
        wpf4 = __ldg((const float4*)pf_w);
    }
    __syncthreads();

    int p = 0;                                // buffer parity
    for (int b = blockIdx.x; b < BATCH; b += GRID_P, p ^= 1) {

        // ---- phase 1: 2 adjacent cells per thread, branchless fp16 gathers ----
        float v4 = 0.f, v5 = 0.f, v6 = 0.f, v7 = 0.f;

        if (t < 113) {                        // cells 2t, 2t+1
            const int* sp = sparse + (long long)b * (12 * CELLS);
            const int* bd = board  + (long long)b * (2 * CELLS);
            const int c0 = 2 * t;
            const bool has1 = (t < 112);

            int2 i0p = __ldg((const int2*)(sp + 10 * CELLS) + t);  // ch10 even base
            int2 b0p = __ldg((const int2*)bd + t);                 // board ch0
            int i1a = __ldg(sp + 11 * CELLS + c0);                 // ch11 odd base
            int b1a = __ldg(bd + CELLS + c0);
            int i1b = 0, b1b = 0;
            if (has1) {
                i1b = __ldg(sp + 11 * CELLS + c0 + 1);
                b1b = __ldg(bd + CELLS + c0 + 1);
            }

            const bool ne0 = (b0p.x + b1a) > 0;
            const int r0a = ne0 ? PCODE : i0p.x;
            const int r0b = (ne0 ? PCODE : i1a) + (PCODE + 1);

            uint2 pol0;
            gather_cell(r0a, r0b, &pol0, v4, v5, v6, v7);
            {
                const int y = c0 / HW, x = c0 % HW;
                feat_s[p][y + 1][x + 1] = pol0;
            }

            if (has1) {
                const bool ne1 = (b0p.y + b1b) > 0;
                const int r1a = ne1 ? PCODE : i0p.y;
                const int r1b = (ne1 ? PCODE : i1b) + (PCODE + 1);
                uint2 pol1;
                gather_cell(r1a, r1b, &pol1, v4, v5, v6, v7);
                const int c1 = c0 + 1;
                const int y = c1 / HW, x = c1 % HW;
                feat_s[p][y + 1][x + 1] = pol1;
            }
        }

        // warp-reduce value channels; lane 0 of each warp stores a float4 partial
        #pragma unroll
        for (int off = 16; off > 0; off >>= 1) {
            v4 += __shfl_down_sync(0xffffffffu, v4, off);
            v5 += __shfl_down_sync(0xffffffffu, v5, off);
            v6 += __shfl_down_sync(0xffffffffu, v6, off);
            v7 += __shfl_down_sync(0xffffffffu, v7, off);
        }
        if ((t & 31) == 0)
            vsum_w[p][t >> 5] = make_float4(v4, v5, v6, v7);
        __syncthreads();   // single barrier per board (double-buffered tile)

        // ---- phase 2: conv, 2 output cells per thread, paired LDS.128 reads ----
        if (t < 120) {
            const int y  = t >> 3;
            const int j  = t & 7;
            const int x0 = j << 1;

            float4 acc0 = wb4, acc1 = wb4;
            #pragma unroll
            for (int r = 0; r < 3; r++) {
                const uint4* rowp = (const uint4*)&feat_s[p][y + r][x0];
                uint4 A = rowp[0];                   // cells x0, x0+1
                uint4 B = rowp[1];                   // cells x0+2, x0+3
                float c[4][4];
                unpack_cell(A.x, A.y, c[0]);
                unpack_cell(A.z, A.w, c[1]);
                unpack_cell(B.x, B.y, c[2]);
                unpack_cell(B.z, B.w, c[3]);
                #pragma unroll
                for (int kx = 0; kx < 3; kx++) {
                    const float4 w = wtap[r * 3 + kx];   // broadcast LDS.128
                    acc0.x = fmaf(w.x, c[kx][0],     acc0.x);
                    acc0.y = fmaf(w.y, c[kx][1],     acc0.y);
                    acc0.z = fmaf(w.z, c[kx][2],     acc0.z);
                    acc0.w = fmaf(w.w, c[kx][3],     acc0.w);
                    acc1.x = fmaf(w.x, c[kx + 1][0], acc1.x);
                    acc1.y = fmaf(w.y, c[kx + 1][1], acc1.y);
                    acc1.z = fmaf(w.z, c[kx + 1][2], acc1.z);
                    acc1.w = fmaf(w.w, c[kx + 1][3], acc1.w);
                }
            }
            float p0 = wpf4.x * fmaxf(acc0.x, 0.f)
                     + wpf4.y * fmaxf(acc0.y, 0.f)
                     + wpf4.z * fmaxf(acc0.z, 0.f)
                     + wpf4.w * fmaxf(acc0.w, 0.f);
            const long long base = (long long)b * CELLS + y * HW + x0;
            out_p[base] = p0;
            if (j < 7) {
                float p1 = wpf4.x * fmaxf(acc1.x, 0.f)
                         + wpf4.y * fmaxf(acc1.y, 0.f)
                         + wpf4.z * fmaxf(acc1.z, 0.f)
                         + wpf4.w * fmaxf(acc1.w, 0.f);
                out_p[base + 1] = p1;
            }
        } else if (t == 120) {
            // ---- value head MLP (thread idle in conv) ----
            float4 s0 = vsum_w[p][0], s1 = vsum_w[p][1];
            float4 s2 = vsum_w[p][2], s3 = vsum_w[p][3];
            const float v0 = s0.x + s1.x + s2.x + s3.x;
            const float v1 = s0.y + s1.y + s2.y + s3.y;
            const float v2 = s0.z + s1.z + s2.z + s3.z;
            const float v3 = s0.w + s1.w + s2.w + s3.w;
            const float4 l1b = __ldg((const float4*)l1_b);
            const float4 l2b = __ldg((const float4*)l2_b);
            float h[4], g[4];
            #pragma unroll
            for (int i = 0; i < 4; i++) {
                const float4 w = __ldg((const float4*)(l1_w + i * 4));
                float a = ((const float*)&l1b)[i];
                a = fmaf(w.x, v0, a); a = fmaf(w.y, v1, a);
                a = fmaf(w.z, v2, a); a = fmaf(w.w, v3, a);
                h[i] = lrelu16(a);
            }
            #pragma unroll
            for (int i = 0; i < 4; i++) {
                const float4 w = __ldg((const float4*)(l2_w + i * 4));
                float a = ((const float*)&l2b)[i];
                a = fmaf(w.x, h[0], a); a = fmaf(w.y, h[1], a);
                a = fmaf(w.z, h[2], a); a = fmaf(w.w, h[3], a);
                g[i] = lrelu16(a);
            }
            #pragma unroll
            for (int k = 0; k < 3; k++) {
                const float4 w = __ldg((const float4*)(vf_w + k * 4));
                float a = __ldg(vf_b + k);
                a = fmaf(w.x, g[0], a); a = fmaf(w.y, g[1], a);
                a = fmaf(w.z, g[2], a); a = fmaf(w.w, g[3], a);
                out_v[(long long)b * 3 + k] = a;
            }
        }
        // no trailing barrier: next iteration writes the other buffer; the next
        // iteration's barrier orders this conv before buffer reuse (2 iters away)
    }
}

extern "C" void kernel_launch(void* const* d_in, const int* in_sizes, int n_in,
                              void* d_out, int out_size) {
    const int*   sparse = (const int*)d_in[0];
    const int*   board  = (const int*)d_in[1];
    const float* W_emb  = (const float*)d_in[2];
    const float* dw_w   = (const float*)d_in[3];
    const float* dw_b   = (const float*)d_in[4];
    const float* pf_w   = (const float*)d_in[5];
    const float* l1_w   = (const float*)d_in[6];
    const float* l1_b   = (const float*)d_in[7];
    const float* l2_w   = (const float*)d_in[8];
    const float* l2_b   = (const float*)d_in[9];
    const float* vf_w   = (const float*)d_in[10];
    const float* vf_b   = (const float*)d_in[11];

    float* out   = (float*)d_out;
    float* out_v = out;                        // (B,3) first (tuple order)
    float* out_p = out + (size_t)BATCH * 3;    // (B,1,15,15) second

    emb_to_half_kernel<<<(NROWS * 2 + 255) / 256, 256>>>(W_emb);

    patnnue_kernel<<<GRID_P, 128>>>(sparse, board, dw_w, dw_b, pf_w,
                                    l1_w, l1_b, l2_w, l2_b, vf_w, vf_b,
                                    out_v, out_p);
}

// round 8
// speedup vs baseline: 2.8917x; 1.1429x over previous
#include <cuda_runtime.h>
#include <cuda_fp16.h>

#define BATCH 32768
#define HW 15
#define CELLS 225          // 15*15
#define PCODE 2380
#define NROWS (2 * (PCODE + 1))   // 4762 embedding rows
#define SMROW 17           // 15 + 2 halo
#define SMCOL 18           // padded to even (16B-aligned uint4 pairs)
#define GRID_P 1184        // 148 SMs * 8 resident blocks
#define WARPS_PER_BLOCK 4
#define TOTAL_WARPS (GRID_P * WARPS_PER_BLOCK)

// fp16 embedding table: row = 8 halves = 16 bytes -> one LDG.128 per row
__device__ __align__(16) __half g_emb[NROWS * 8];

__global__ void __launch_bounds__(256)
emb_to_half_kernel(const float* __restrict__ W_emb) {
    int i = blockIdx.x * 256 + threadIdx.x;          // one half4 (4 floats) per thread
    if (i < NROWS * 2) {
        float4 f = __ldg((const float4*)(W_emb + (size_t)i * 4));
        __half2* dst = (__half2*)(g_emb + (size_t)i * 4);
        dst[0] = __floats2half2_rn(f.x, f.y);
        dst[1] = __floats2half2_rn(f.z, f.w);
    }
}

__device__ __forceinline__ float lrelu16(float x) {
    return x >= 0.f ? x : x * 0.0625f;
}

__device__ __forceinline__ void unpack_cell(unsigned lo, unsigned hi, float* out) {
    float2 a = __half22float2(*(__half2*)&lo);
    float2 b = __half22float2(*(__half2*)&hi);
    out[0] = a.x; out[1] = a.y; out[2] = b.x; out[3] = b.y;
}

// gather one cell's two fp16 embedding rows, emit packed policy half4 + value f32x4
__device__ __forceinline__ void gather_cell(int r0, int r1, uint2* pol,
                                            float& v4, float& v5, float& v6, float& v7) {
    uint4 e0 = __ldg((const uint4*)(g_emb + (size_t)r0 * 8));
    uint4 e1 = __ldg((const uint4*)(g_emb + (size_t)r1 * 8));
    float2 p01 = __half22float2(*(__half2*)&e0.x);
    float2 q01 = __half22float2(*(__half2*)&e1.x);
    float2 p23 = __half22float2(*(__half2*)&e0.y);
    float2 q23 = __half22float2(*(__half2*)&e1.y);
    float2 a45 = __half22float2(*(__half2*)&e0.z);
    float2 b45 = __half22float2(*(__half2*)&e1.z);
    float2 a67 = __half22float2(*(__half2*)&e0.w);
    float2 b67 = __half22float2(*(__half2*)&e1.w);
    __half2 hp0 = __floats2half2_rn(p01.x + q01.x, p01.y + q01.y);
    __half2 hp1 = __floats2half2_rn(p23.x + q23.x, p23.y + q23.y);
    *pol = make_uint2(*(unsigned*)&hp0, *(unsigned*)&hp1);
    v4 += a45.x + b45.x;
    v5 += a45.y + b45.y;
    v6 += a67.x + b67.x;
    v7 += a67.y + b67.y;
}

__global__ void __launch_bounds__(128, 8)
patnnue_kernel(const int* __restrict__ sparse,   // (B,12,15,15)
               const int* __restrict__ board,    // (B,2,15,15)
               const float* __restrict__ dw_w,   // (4,1,3,3)
               const float* __restrict__ dw_b,   // (4,)
               const float* __restrict__ pf_w,   // (1,4,1,1)
               const float* __restrict__ l1_w,   // (4,4)
               const float* __restrict__ l1_b,   // (4,)
               const float* __restrict__ l2_w,   // (4,4)
               const float* __restrict__ l2_b,   // (4,)
               const float* __restrict__ vf_w,   // (3,4)
               const float* __restrict__ vf_b,   // (3,)
               float* __restrict__ out_v,        // (B,3)
               float* __restrict__ out_p)        // (B,1,15,15)
{
    const int t    = threadIdx.x;
    const int w    = t >> 5;
    const int lane = t & 31;

    __shared__ __align__(16) uint2 feat_s[WARPS_PER_BLOCK][SMROW][SMCOL]; // per-warp tile
    __shared__ float4 wtap[9];               // dw weights, tap-major across channels
    __shared__ float4 wb4;                   // dw_b
    __shared__ float4 wpf4;                  // pf_w

    // ---- one-time init: zero all tiles (halo stays zero forever) + weights ----
    uint2* fz = &feat_s[0][0][0];
    for (int i = t; i < WARPS_PER_BLOCK * SMROW * SMCOL; i += 128)
        fz[i] = make_uint2(0u, 0u);
    if (t < 36) {
        float wv = __ldg(dw_w + t);
        ((float*)&wtap[t % 9])[t / 9] = wv;  // transpose to tap-major
    } else if (t == 36) {
        wb4  = __ldg((const float4*)dw_b);
    } else if (t == 37) {
        wpf4 = __ldg((const float4*)pf_w);
    }
    __syncthreads();                          // the ONLY block-wide barrier

    uint2 (*tile)[SMCOL] = feat_s[w];
    const int gw = blockIdx.x * WARPS_PER_BLOCK + w;

    for (int b = gw; b < BATCH; b += TOTAL_WARPS) {
        const int* sp = sparse + (long long)b * (12 * CELLS);
        const int* bd = board  + (long long)b * (2 * CELLS);

        // ---- phase 1: gather, lane strides cells ----
        float v4 = 0.f, v5 = 0.f, v6 = 0.f, v7 = 0.f;
        #pragma unroll
        for (int k = 0; k < 8; k++) {
            const int c = lane + 32 * k;
            if (c < CELLS) {
                const int i0 = __ldg(sp + 10 * CELLS + c);
                const int i1 = __ldg(sp + 11 * CELLS + c);
                const bool ne = (__ldg(bd + c) + __ldg(bd + CELLS + c)) > 0;
                const int r0 = ne ? PCODE : i0;
                const int r1 = (ne ? PCODE : i1) + (PCODE + 1);
                uint2 pol;
                gather_cell(r0, r1, &pol, v4, v5, v6, v7);
                tile[c / HW + 1][c % HW + 1] = pol;
            }
        }
        __syncwarp();

        // ---- phase 2: conv, lane strides pair-slots (paired LDS.128 reads) ----
        #pragma unroll
        for (int k = 0; k < 4; k++) {
            const int slot = lane + 32 * k;
            if (slot < 120) {
                const int y  = slot >> 3;
                const int j  = slot & 7;
                const int x0 = j << 1;

                float4 acc0 = wb4, acc1 = wb4;
                #pragma unroll
                for (int r = 0; r < 3; r++) {
                    const uint4* rowp = (const uint4*)&tile[y + r][x0];
                    uint4 A = rowp[0];                   // cells x0, x0+1
                    uint4 B = rowp[1];                   // cells x0+2, x0+3
                    float c4[4][4];
                    unpack_cell(A.x, A.y, c4[0]);
                    unpack_cell(A.z, A.w, c4[1]);
                    unpack_cell(B.x, B.y, c4[2]);
                    unpack_cell(B.z, B.w, c4[3]);
                    #pragma unroll
                    for (int kx = 0; kx < 3; kx++) {
                        const float4 wv = wtap[r * 3 + kx];   // broadcast LDS.128
                        acc0.x = fmaf(wv.x, c4[kx][0],     acc0.x);
                        acc0.y = fmaf(wv.y, c4[kx][1],     acc0.y);
                        acc0.z = fmaf(wv.z, c4[kx][2],     acc0.z);
                        acc0.w = fmaf(wv.w, c4[kx][3],     acc0.w);
                        acc1.x = fmaf(wv.x, c4[kx + 1][0], acc1.x);
                        acc1.y = fmaf(wv.y, c4[kx + 1][1], acc1.y);
                        acc1.z = fmaf(wv.z, c4[kx + 1][2], acc1.z);
                        acc1.w = fmaf(wv.w, c4[kx + 1][3], acc1.w);
                    }
                }
                float p0 = wpf4.x * fmaxf(acc0.x, 0.f)
                         + wpf4.y * fmaxf(acc0.y, 0.f)
                         + wpf4.z * fmaxf(acc0.z, 0.f)
                         + wpf4.w * fmaxf(acc0.w, 0.f);
                const long long base = (long long)b * CELLS + y * HW + x0;
                out_p[base] = p0;
                if (j < 7) {
                    float p1 = wpf4.x * fmaxf(acc1.x, 0.f)
                             + wpf4.y * fmaxf(acc1.y, 0.f)
                             + wpf4.z * fmaxf(acc1.z, 0.f)
                             + wpf4.w * fmaxf(acc1.w, 0.f);
                    out_p[base + 1] = p1;
                }
            }
        }

        // ---- value reduce (warp shuffles) + MLP on lane 0 ----
        #pragma unroll
        for (int off = 16; off > 0; off >>= 1) {
            v4 += __shfl_down_sync(0xffffffffu, v4, off);
            v5 += __shfl_down_sync(0xffffffffu, v5, off);
            v6 += __shfl_down_sync(0xffffffffu, v6, off);
            v7 += __shfl_down_sync(0xffffffffu, v7, off);
        }
        if (lane == 0) {
            const float4 l1b = __ldg((const float4*)l1_b);
            const float4 l2b = __ldg((const float4*)l2_b);
            float h[4], g[4];
            #pragma unroll
            for (int i = 0; i < 4; i++) {
                const float4 wv = __ldg((const float4*)(l1_w + i * 4));
                float a = ((const float*)&l1b)[i];
                a = fmaf(wv.x, v4, a); a = fmaf(wv.y, v5, a);
                a = fmaf(wv.z, v6, a); a = fmaf(wv.w, v7, a);
                h[i] = lrelu16(a);
            }
            #pragma unroll
            for (int i = 0; i < 4; i++) {
                const float4 wv = __ldg((const float4*)(l2_w + i * 4));
                float a = ((const float*)&l2b)[i];
                a = fmaf(wv.x, h[0], a); a = fmaf(wv.y, h[1], a);
                a = fmaf(wv.z, h[2], a); a = fmaf(wv.w, h[3], a);
                g[i] = lrelu16(a);
            }
            #pragma unroll
            for (int k = 0; k < 3; k++) {
                const float4 wv = __ldg((const float4*)(vf_w + k * 4));
                float a = __ldg(vf_b + k);
                a = fmaf(wv.x, g[0], a); a = fmaf(wv.y, g[1], a);
                a = fmaf(wv.z, g[2], a); a = fmaf(wv.w, g[3], a);
                out_v[(long long)b * 3 + k] = a;
            }
        }
        __syncwarp();     // conv reads done before next board overwrites tile
    }
}

extern "C" void kernel_launch(void* const* d_in, const int* in_sizes, int n_in,
                              void* d_out, int out_size) {
    const int*   sparse = (const int*)d_in[0];
    const int*   board  = (const int*)d_in[1];
    const float* W_emb  = (const float*)d_in[2];
    const float* dw_w   = (const float*)d_in[3];
    const float* dw_b   = (const float*)d_in[4];
    const float* pf_w   = (const float*)d_in[5];
    const float* l1_w   = (const float*)d_in[6];
    const float* l1_b   = (const float*)d_in[7];
    const float* l2_w   = (const float*)d_in[8];
    const float* l2_b   = (const float*)d_in[9];
    const float* vf_w   = (const float*)d_in[10];
    const float* vf_b   = (const float*)d_in[11];

    float* out   = (float*)d_out;
    float* out_v = out;                        // (B,3) first (tuple order)
    float* out_p = out + (size_t)BATCH * 3;    // (B,1,15,15) second

    emb_to_half_kernel<<<(NROWS * 2 + 255) / 256, 256>>>(W_emb);

    patnnue_kernel<<<GRID_P, 128>>>(sparse, board, dw_w, dw_b, pf_w,
                                    l1_w, l1_b, l2_w, l2_b, vf_w, vf_b,
                                    out_v, out_p);
}

// round 9
// speedup vs baseline: 2.9697x; 1.0270x over previous
#include <cuda_runtime.h>
#include <cuda_fp16.h>

#define BATCH 32768
#define HW 15
#define CELLS 225          // 15*15
#define PCODE 2380
#define NROWS (2 * (PCODE + 1))   // 4762 embedding rows
#define SMROW 17           // 15 + 2 halo
#define SMCOL 18           // padded (9 uint4 per row; col16 halo, col17 pad, both 0)
#define GRID_P 1184        // 148 SMs * 8 resident blocks
#define WARPS_PER_BLOCK 4
#define TOTAL_WARPS (GRID_P * WARPS_PER_BLOCK)

// fp16 embedding table: row = 8 halves = 16 bytes -> one LDG.128 per row
__device__ __align__(16) __half g_emb[NROWS * 8];

__global__ void __launch_bounds__(256)
emb_to_half_kernel(const float* __restrict__ W_emb) {
    int i = blockIdx.x * 256 + threadIdx.x;          // one half4 (4 floats) per thread
    if (i < NROWS * 2) {
        float4 f = __ldg((const float4*)(W_emb + (size_t)i * 4));
        __half2* dst = (__half2*)(g_emb + (size_t)i * 4);
        dst[0] = __floats2half2_rn(f.x, f.y);
        dst[1] = __floats2half2_rn(f.z, f.w);
    }
}

__device__ __forceinline__ float lrelu16(float x) {
    return x >= 0.f ? x : x * 0.0625f;
}

__device__ __forceinline__ void unpack_cell(unsigned lo, unsigned hi, float* out) {
    float2 a = __half22float2(*(__half2*)&lo);
    float2 b = __half22float2(*(__half2*)&hi);
    out[0] = a.x; out[1] = a.y; out[2] = b.x; out[3] = b.y;
}

// gather one cell's two fp16 embedding rows, emit packed policy half4 + value f32x4
__device__ __forceinline__ void gather_cell(int r0, int r1, uint2* pol,
                                            float& v4, float& v5, float& v6, float& v7) {
    uint4 e0 = __ldg((const uint4*)(g_emb + (size_t)r0 * 8));
    uint4 e1 = __ldg((const uint4*)(g_emb + (size_t)r1 * 8));
    float2 p01 = __half22float2(*(__half2*)&e0.x);
    float2 q01 = __half22float2(*(__half2*)&e1.x);
    float2 p23 = __half22float2(*(__half2*)&e0.y);
    float2 q23 = __half22float2(*(__half2*)&e1.y);
    float2 a45 = __half22float2(*(__half2*)&e0.z);
    float2 b45 = __half22float2(*(__half2*)&e1.z);
    float2 a67 = __half22float2(*(__half2*)&e0.w);
    float2 b67 = __half22float2(*(__half2*)&e1.w);
    __half2 hp0 = __floats2half2_rn(p01.x + q01.x, p01.y + q01.y);
    __half2 hp1 = __floats2half2_rn(p23.x + q23.x, p23.y + q23.y);
    *pol = make_uint2(*(unsigned*)&hp0, *(unsigned*)&hp1);
    v4 += a45.x + b45.x;
    v5 += a45.y + b45.y;
    v6 += a67.x + b67.x;
    v7 += a67.y + b67.y;
}

__global__ void __launch_bounds__(128, 8)
patnnue_kernel(const int* __restrict__ sparse,   // (B,12,15,15)
               const int* __restrict__ board,    // (B,2,15,15)
               const float* __restrict__ dw_w,   // (4,1,3,3)
               const float* __restrict__ dw_b,   // (4,)
               const float* __restrict__ pf_w,   // (1,4,1,1)
               const float* __restrict__ l1_w,   // (4,4)
               const float* __restrict__ l1_b,   // (4,)
               const float* __restrict__ l2_w,   // (4,4)
               const float* __restrict__ l2_b,   // (4,)
               const float* __restrict__ vf_w,   // (3,4)
               const float* __restrict__ vf_b,   // (3,)
               float* __restrict__ out_v,        // (B,3)
               float* __restrict__ out_p)        // (B,1,15,15)
{
    const int t    = threadIdx.x;
    const int w    = t >> 5;
    const int lane = t & 31;

    __shared__ __align__(16) uint2 feat_s[WARPS_PER_BLOCK][SMROW][SMCOL]; // per-warp tile
    __shared__ float4 wtap[9];               // dw weights, tap-major across channels
    __shared__ float4 wb4;                   // dw_b
    __shared__ float4 wpf4;                  // pf_w

    // ---- one-time init: zero all tiles (halo stays zero forever) + weights ----
    uint2* fz = &feat_s[0][0][0];
    for (int i = t; i < WARPS_PER_BLOCK * SMROW * SMCOL; i += 128)
        fz[i] = make_uint2(0u, 0u);
    if (t < 36) {
        float wv = __ldg(dw_w + t);
        ((float*)&wtap[t % 9])[t / 9] = wv;  // transpose to tap-major
    } else if (t == 36) {
        wb4  = __ldg((const float4*)dw_b);
    } else if (t == 37) {
        wpf4 = __ldg((const float4*)pf_w);
    }
    __syncthreads();                          // the ONLY block-wide barrier

    uint2 (*tile)[SMCOL] = feat_s[w];
    const int gw = blockIdx.x * WARPS_PER_BLOCK + w;

    for (int b = gw; b < BATCH; b += TOTAL_WARPS) {
        const int* sp = sparse + (long long)b * (12 * CELLS);
        const int* bd = board  + (long long)b * (2 * CELLS);

        // ---- phase 1: gather, lane strides cells ----
        float v4 = 0.f, v5 = 0.f, v6 = 0.f, v7 = 0.f;
        #pragma unroll
        for (int k = 0; k < 8; k++) {
            const int c = lane + 32 * k;
            if (c < CELLS) {
                const int i0 = __ldg(sp + 10 * CELLS + c);
                const int i1 = __ldg(sp + 11 * CELLS + c);
                const bool ne = (__ldg(bd + c) + __ldg(bd + CELLS + c)) > 0;
                const int r0 = ne ? PCODE : i0;
                const int r1 = (ne ? PCODE : i1) + (PCODE + 1);
                uint2 pol;
                gather_cell(r0, r1, &pol, v4, v5, v6, v7);
                tile[c / HW + 1][c % HW + 1] = pol;
            }
        }
        __syncwarp();

        // ---- phase 2: conv, 4 output cells per thread (60 slots, 2 iterations) ----
        #pragma unroll
        for (int k = 0; k < 2; k++) {
            const int slot = lane + 32 * k;
            if (slot < 60) {
                const int y  = slot >> 2;           // 0..14
                const int j  = slot & 3;            // 0..3
                const int x0 = j << 2;              // 0,4,8,12

                float4 acc0 = wb4, acc1 = wb4, acc2 = wb4, acc3 = wb4;
                #pragma unroll
                for (int r = 0; r < 3; r++) {
                    const uint4* rowp = (const uint4*)&tile[y + r][0];
                    uint4 A = rowp[2 * j];          // cells x0-1, x0
                    uint4 B = rowp[2 * j + 1];      // cells x0+1, x0+2
                    uint4 C = rowp[2 * j + 2];      // cells x0+3, x0+4
                    float c6[6][4];
                    unpack_cell(A.x, A.y, c6[0]);
                    unpack_cell(A.z, A.w, c6[1]);
                    unpack_cell(B.x, B.y, c6[2]);
                    unpack_cell(B.z, B.w, c6[3]);
                    unpack_cell(C.x, C.y, c6[4]);
                    unpack_cell(C.z, C.w, c6[5]);
                    #pragma unroll
                    for (int kx = 0; kx < 3; kx++) {
                        const float4 wv = wtap[r * 3 + kx];   // broadcast LDS.128
                        acc0.x = fmaf(wv.x, c6[kx][0],     acc0.x);
                        acc0.y = fmaf(wv.y, c6[kx][1],     acc0.y);
                        acc0.z = fmaf(wv.z, c6[kx][2],     acc0.z);
                        acc0.w = fmaf(wv.w, c6[kx][3],     acc0.w);
                        acc1.x = fmaf(wv.x, c6[kx + 1][0], acc1.x);
                        acc1.y = fmaf(wv.y, c6[kx + 1][1], acc1.y);
                        acc1.z = fmaf(wv.z, c6[kx + 1][2], acc1.z);
                        acc1.w = fmaf(wv.w, c6[kx + 1][3], acc1.w);
                        acc2.x = fmaf(wv.x, c6[kx + 2][0], acc2.x);
                        acc2.y = fmaf(wv.y, c6[kx + 2][1], acc2.y);
                        acc2.z = fmaf(wv.z, c6[kx + 2][2], acc2.z);
                        acc2.w = fmaf(wv.w, c6[kx + 2][3], acc2.w);
                        acc3.x = fmaf(wv.x, c6[kx + 3][0], acc3.x);
                        acc3.y = fmaf(wv.y, c6[kx + 3][1], acc3.y);
                        acc3.z = fmaf(wv.z, c6[kx + 3][2], acc3.z);
                        acc3.w = fmaf(wv.w, c6[kx + 3][3], acc3.w);
                    }
                }
                const long long base = (long long)b * CELLS + y * HW + x0;
                out_p[base + 0] = wpf4.x * fmaxf(acc0.x, 0.f)
                                + wpf4.y * fmaxf(acc0.y, 0.f)
                                + wpf4.z * fmaxf(acc0.z, 0.f)
                                + wpf4.w * fmaxf(acc0.w, 0.f);
                out_p[base + 1] = wpf4.x * fmaxf(acc1.x, 0.f)
                                + wpf4.y * fmaxf(acc1.y, 0.f)
                                + wpf4.z * fmaxf(acc1.z, 0.f)
                                + wpf4.w * fmaxf(acc1.w, 0.f);
                out_p[base + 2] = wpf4.x * fmaxf(acc2.x, 0.f)
                                + wpf4.y * fmaxf(acc2.y, 0.f)
                                + wpf4.z * fmaxf(acc2.z, 0.f)
                                + wpf4.w * fmaxf(acc2.w, 0.f);
                if (j < 3) {                        // x0+3 = 15 invalid for j==3
                    out_p[base + 3] = wpf4.x * fmaxf(acc3.x, 0.f)
                                    + wpf4.y * fmaxf(acc3.y, 0.f)
                                    + wpf4.z * fmaxf(acc3.z, 0.f)
                                    + wpf4.w * fmaxf(acc3.w, 0.f);
                }
            }
        }

        // ---- value reduce (warp shuffles) + MLP on lane 0 ----
        #pragma unroll
        for (int off = 16; off > 0; off >>= 1) {
            v4 += __shfl_down_sync(0xffffffffu, v4, off);
            v5 += __shfl_down_sync(0xffffffffu, v5, off);
            v6 += __shfl_down_sync(0xffffffffu, v6, off);
            v7 += __shfl_down_sync(0xffffffffu, v7, off);
        }
        if (lane == 0) {
            const float4 l1b = __ldg((const float4*)l1_b);
            const float4 l2b = __ldg((const float4*)l2_b);
            float h[4], g[4];
            #pragma unroll
            for (int i = 0; i < 4; i++) {
                const float4 wv = __ldg((const float4*)(l1_w + i * 4));
                float a = ((const float*)&l1b)[i];
                a = fmaf(wv.x, v4, a); a = fmaf(wv.y, v5, a);
                a = fmaf(wv.z, v6, a); a = fmaf(wv.w, v7, a);
                h[i] = lrelu16(a);
            }
            #pragma unroll
            for (int i = 0; i < 4; i++) {
                const float4 wv = __ldg((const float4*)(l2_w + i * 4));
                float a = ((const float*)&l2b)[i];
                a = fmaf(wv.x, h[0], a); a = fmaf(wv.y, h[1], a);
                a = fmaf(wv.z, h[2], a); a = fmaf(wv.w, h[3], a);
                g[i] = lrelu16(a);
            }
            #pragma unroll
            for (int k = 0; k < 3; k++) {
                const float4 wv = __ldg((const float4*)(vf_w + k * 4));
                float a = __ldg(vf_b + k);
                a = fmaf(wv.x, g[0], a); a = fmaf(wv.y, g[1], a);
                a = fmaf(wv.z, g[2], a); a = fmaf(wv.w, g[3], a);
                out_v[(long long)b * 3 + k] = a;
            }
        }
        __syncwarp();     // conv reads done before next board overwrites tile
    }
}

extern "C" void kernel_launch(void* const* d_in, const int* in_sizes, int n_in,
                              void* d_out, int out_size) {
    const int*   sparse = (const int*)d_in[0];
    const int*   board  = (const int*)d_in[1];
    const float* W_emb  = (const float*)d_in[2];
    const float* dw_w   = (const float*)d_in[3];
    const float* dw_b   = (const float*)d_in[4];
    const float* pf_w   = (const float*)d_in[5];
    const float* l1_w   = (const float*)d_in[6];
    const float* l1_b   = (const float*)d_in[7];
    const float* l2_w   = (const float*)d_in[8];
    const float* l2_b   = (const float*)d_in[9];
    const float* vf_w   = (const float*)d_in[10];
    const float* vf_b   = (const float*)d_in[11];

    float* out   = (float*)d_out;
    float* out_v = out;                        // (B,3) first (tuple order)
    float* out_p = out + (size_t)BATCH * 3;    // (B,1,15,15) second

    emb_to_half_kernel<<<(NROWS * 2 + 255) / 256, 256>>>(W_emb);

    patnnue_kernel<<<GRID_P, 128>>>(sparse, board, dw_w, dw_b, pf_w,
                                    l1_w, l1_b, l2_w, l2_b, vf_w, vf_b,
                                    out_v, out_p);
}